// round 16
// baseline (speedup 1.0000x reference)
#include <cuda_runtime.h>
#include <cuda_fp16.h>
#include <cstdint>

#define N_MAX 8192
#define D_MAX 256
#define BM 128
#define BN 128
#define BK 64                     // f16 K per stage
#define NBUF 3
#define NCTA 296                  // persistent: 2 CTAs x 148 SMs
#define NTHREADS 256
#define MARGIN 0.5f

__device__ __half g_xh[N_MAX * D_MAX];
__device__ float g_sq[N_MAX];
__device__ int   g_is64;

// dynamic smem (bytes): 3 x 32KB stage bufs + 2 x 2KB meta bufs + red
#define STAGE_BYTES 32768
#define SM_META   (NBUF * STAGE_BYTES)     // 98304
#define META_BYTES 2048                    // sqi | ti | sqj | tj (512 each)
#define SM_RED    (SM_META + 2 * META_BYTES)
#define SM_TOTAL  (SM_RED + NTHREADS * 4)  // 103424 B (~101 KB) -> 2 CTAs/SM

__device__ __forceinline__ uint32_t smem_u32(const void* p) {
    uint32_t a;
    asm("{ .reg .u64 t; cvta.to.shared.u64 t, %1; cvt.u32.u64 %0, t; }" : "=r"(a) : "l"(p));
    return a;
}

__device__ __forceinline__ void decode_tile(int t, int nt, int& bi, int& bj) {
    int b = (int)((2.0f * nt + 1.0f -
                   sqrtf((2.0f * nt + 1.0f) * (2.0f * nt + 1.0f) - 8.0f * t)) * 0.5f);
    if (b < 0) b = 0;
    if (b > nt - 1) b = nt - 1;
    while (b + 1 <= nt - 1 && (b + 1) * nt - ((b + 1) * b) / 2 <= t) b++;
    while (b * nt - (b * (b - 1)) / 2 > t) b--;
    bi = b;
    bj = b + (t - (b * nt - (b * (b - 1)) / 2));
}

// ---------------------------------------------------------------------------
// fused prelim: zero out + int64 detect + exact fp32 norms + f16 copy
// ---------------------------------------------------------------------------
__global__ void cvtsq_kernel(const float* __restrict__ x,
                             const unsigned int* __restrict__ t, int n,
                             float* __restrict__ out) {
    if (blockIdx.x == 0 && threadIdx.x < 32) {
        int lane = threadIdx.x;
        unsigned bad = t[2 * lane + 1] | t[2 * (lane + 32) + 1];
        unsigned ball = __ballot_sync(0xffffffffu, bad != 0u);
        if (lane == 0) { g_is64 = (ball == 0u); out[0] = 0.0f; }
    }

    int row  = blockIdx.x * (blockDim.x >> 5) + (threadIdx.x >> 5);
    int lane = threadIdx.x & 31;
    if (row >= n) return;
    const float* p = x + (size_t)row * D_MAX;

    float4 v0 = *(const float4*)(p + lane * 4);
    float4 v1 = *(const float4*)(p + 128 + lane * 4);

    float s = v0.x * v0.x + v0.y * v0.y + v0.z * v0.z + v0.w * v0.w
            + v1.x * v1.x + v1.y * v1.y + v1.z * v1.z + v1.w * v1.w;
    #pragma unroll
    for (int o = 16; o > 0; o >>= 1) s += __shfl_xor_sync(0xffffffffu, s, o);
    if (lane == 0) g_sq[row] = s;

    __half* dst = g_xh + (size_t)row * D_MAX;
    *(__half2*)(dst + lane * 4)           = __floats2half2_rn(v0.x, v0.y);
    *(__half2*)(dst + lane * 4 + 2)       = __floats2half2_rn(v0.z, v0.w);
    *(__half2*)(dst + 128 + lane * 4)     = __floats2half2_rn(v1.x, v1.y);
    *(__half2*)(dst + 128 + lane * 4 + 2) = __floats2half2_rn(v1.z, v1.w);
}

// ---------------------------------------------------------------------------
// Persistent f16 mma.sync fused gram + loss. 296 CTAs, each walks tiles
// t, t+296, ... of the 2080-tile upper triangle. Continuous cp.async stage
// stream across tile boundaries (3 bufs, lookahead 2, global stage index);
// meta double-buffered and prefetched one tile ahead. Inner machinery = R11:
// 8 warps (2m x 4n), warp 64x32, frag double-buffer, 128B-stride swizzle.
// ---------------------------------------------------------------------------
__global__ __launch_bounds__(NTHREADS, 2)
void loss_kernel(const void* __restrict__ tgt_raw, float* __restrict__ out,
                 int nt, int ntri, float scale) {
    extern __shared__ char smem[];
    float* s_red = (float*)(smem + SM_RED);

    const int tid  = threadIdx.x;
    const int wid  = tid >> 5;
    const int lane = tid & 31;
    const uint32_t smem_base = smem_u32(smem);

    const long long* t64p = (const long long*)tgt_raw;
    const int*       t32p = (const int*)tgt_raw;
    const bool is64 = (g_is64 != 0);

    const int NT = (ntri - blockIdx.x + NCTA - 1) / NCTA;   // tiles for this CTA
    const int G  = NT * 4;                                  // global stages

    // ---- load cursor ----
    int t_load = blockIdx.x;
    int l_bi, l_bj;
    decode_tile(t_load, nt, l_bi, l_bj);

    auto store_meta = [&](int mbuf, int bi_, int bj_) {
        char* mb = smem + SM_META + mbuf * META_BYTES;
        if (tid < BM) {
            ((float*)mb)[tid]        = g_sq[bi_ * BM + tid];
            ((int*)(mb + 512))[tid]  = is64 ? (int)t64p[bi_ * BM + tid] : t32p[bi_ * BM + tid];
        } else {
            int tt = tid - BM;
            ((float*)(mb + 1024))[tt] = g_sq[bj_ * BN + tt];
            ((int*)(mb + 1536))[tt]   = is64 ? (int)t64p[bj_ * BN + tt] : t32p[bj_ * BN + tt];
        }
    };

    auto issue_load = [&](int S) {
        const int kb = S & 3;
        if (kb == 0 && S > 0) {          // advance cursor to next tile
            t_load += NCTA;
            decode_tile(t_load, nt, l_bi, l_bj);
            store_meta((S >> 2) & 1, l_bi, l_bj);
        }
        const __half* xa = g_xh + (size_t)l_bi * BM * D_MAX;
        const __half* xb = g_xh + (size_t)l_bj * BN * D_MAX;
        const int k0 = kb * BK;
        const uint32_t sA = smem_base + (S % NBUF) * STAGE_BYTES;
        const uint32_t sB = sA + 16384;
        #pragma unroll
        for (int u = 0; u < 4; u++) {
            int idx = tid * 4 + u;
            int row = idx >> 3;
            int c   = idx & 7;
            uint32_t sw = row * 128 + (((c ^ (row & 7)) & 7) << 4);
            asm volatile("cp.async.cg.shared.global [%0], [%1], 16;"
                         :: "r"(sA + sw), "l"((const void*)(xa + row * D_MAX + k0 + c * 8)) : "memory");
            asm volatile("cp.async.cg.shared.global [%0], [%1], 16;"
                         :: "r"(sB + sw), "l"((const void*)(xb + row * D_MAX + k0 + c * 8)) : "memory");
        }
        asm volatile("cp.async.commit_group;" ::: "memory");
    };

    // prologue: meta(0) + stages 0,1
    store_meta(0, l_bi, l_bj);
    issue_load(0);
    issue_load(1);

    // warp grid 2m x 4n; warp tile 64 x 32 (R11)
    const int mbase = (wid >> 2) * 64;
    const int nbase = (wid & 3) * 32;

    const int a_roff = ((lane >> 3) & 1) * 8 + (lane & 7);
    const int a_coff = (lane >> 4);
    const int b_roff = ((lane >> 4) & 1) * 8 + (lane & 7);
    const int b_coff = ((lane >> 3) & 1);

    uint32_t aF[2][4][4];
    uint32_t bF[2][4][2];
    uint32_t acc[4][4][2];

    auto ldm_frags = [&](int d, uint32_t sA, uint32_t sB, int s) {
        #pragma unroll
        for (int mt = 0; mt < 4; mt++) {
            int r  = mbase + mt * 16 + a_roff;
            int ch = a_coff + 2 * s;
            uint32_t addr = sA + r * 128 + (((ch ^ (r & 7)) & 7) << 4);
            asm volatile("ldmatrix.sync.aligned.m8n8.x4.shared.b16 {%0,%1,%2,%3}, [%4];"
                         : "=r"(aF[d][mt][0]), "=r"(aF[d][mt][1]),
                           "=r"(aF[d][mt][2]), "=r"(aF[d][mt][3])
                         : "r"(addr));
        }
        #pragma unroll
        for (int p = 0; p < 2; p++) {
            int r  = nbase + p * 16 + b_roff;
            int ch = b_coff + 2 * s;
            uint32_t addr = sB + r * 128 + (((ch ^ (r & 7)) & 7) << 4);
            asm volatile("ldmatrix.sync.aligned.m8n8.x4.shared.b16 {%0,%1,%2,%3}, [%4];"
                         : "=r"(bF[d][2 * p][0]), "=r"(bF[d][2 * p][1]),
                           "=r"(bF[d][2 * p + 1][0]), "=r"(bF[d][2 * p + 1][1])
                         : "r"(addr));
        }
    };
    auto mma_all = [&](int d) {
        #pragma unroll
        for (int mt = 0; mt < 4; mt++)
            #pragma unroll
            for (int ntl = 0; ntl < 4; ntl++)
                asm volatile(
                    "mma.sync.aligned.m16n8k16.row.col.f16.f16.f16.f16 "
                    "{%0,%1}, {%2,%3,%4,%5}, {%6,%7}, {%0,%1};"
                    : "+r"(acc[mt][ntl][0]), "+r"(acc[mt][ntl][1])
                    : "r"(aF[d][mt][0]), "r"(aF[d][mt][1]),
                      "r"(aF[d][mt][2]), "r"(aF[d][mt][3]),
                      "r"(bF[d][ntl][0]), "r"(bF[d][ntl][1]));
    };

    const int gid = lane >> 2;
    const int tig = lane & 3;
    float lsum = 0.0f;
    int t_cur = blockIdx.x;

    for (int T = 0; T < NT; T++) {
        int c_bi, c_bj;
        decode_tile(t_cur, nt, c_bi, c_bj);

        #pragma unroll
        for (int mt = 0; mt < 4; mt++)
            #pragma unroll
            for (int ntl = 0; ntl < 4; ntl++) { acc[mt][ntl][0] = 0u; acc[mt][ntl][1] = 0u; }

        #pragma unroll
        for (int kb = 0; kb < 4; kb++) {
            const int S = 4 * T + kb;
            if (S + 1 < G) { asm volatile("cp.async.wait_group 1;" ::: "memory"); }
            else           { asm volatile("cp.async.wait_group 0;" ::: "memory"); }
            __syncthreads();                 // stage S ready; buf (S+2)%3 free
            if (S + 2 < G) issue_load(S + 2);

            const uint32_t sA = smem_base + (S % NBUF) * STAGE_BYTES;
            const uint32_t sB = sA + 16384;
            ldm_frags(0, sA, sB, 0);
            #pragma unroll
            for (int ks = 0; ks < 4; ks++) {
                const int cur = ks & 1;
                if (ks < 3) ldm_frags(cur ^ 1, sA, sB, ks + 1);
                mma_all(cur);
            }
        }

        // epilogue (meta buffer T&1) — overlaps next tile's in-flight loads
        const char* mb = smem + SM_META + (T & 1) * META_BYTES;
        const float* s_sqi = (const float*)mb;
        const int*   s_ti  = (const int*)(mb + 512);
        const float* s_sqj = (const float*)(mb + 1024);
        const int*   s_tj  = (const int*)(mb + 1536);
        const bool diag = (c_bi == c_bj);
        #pragma unroll
        for (int mt = 0; mt < 4; mt++) {
            #pragma unroll
            for (int ntl = 0; ntl < 4; ntl++) {
                #pragma unroll
                for (int h = 0; h < 2; h++) {
                    float2 gp = __half22float2(*(const __half2*)&acc[mt][ntl][h]);
                    int m = mbase + mt * 16 + gid + h * 8;
                    float sqm = s_sqi[m];
                    int   tm  = s_ti[m];
                    #pragma unroll
                    for (int q = 0; q < 2; q++) {
                        int nn = nbase + ntl * 8 + 2 * tig + q;
                        float g    = q ? gp.y : gp.x;
                        float dist = fmaf(-2.0f, g, sqm + s_sqj[nn]);
                        float val  = (tm == s_tj[nn]) ? dist : fmaxf(MARGIN - dist, 0.0f);
                        if (!diag || (m < nn)) lsum += val;
                    }
                }
            }
        }
        t_cur += NCTA;
    }

    // final block reduce + one atomic per CTA
    s_red[tid] = lsum;
    __syncthreads();
    #pragma unroll
    for (int s = NTHREADS / 2; s > 32; s >>= 1) {
        if (tid < s) s_red[tid] += s_red[tid + s];
        __syncthreads();
    }
    if (tid < 32) {
        float v = s_red[tid] + s_red[tid + 32];
        #pragma unroll
        for (int o = 16; o > 0; o >>= 1) v += __shfl_xor_sync(0xffffffffu, v, o);
        if (tid == 0) atomicAdd(out, v * scale);
    }
}

extern "C" void kernel_launch(void* const* d_in, const int* in_sizes, int n_in,
                              void* d_out, int out_size) {
    const float* x   = (const float*)d_in[0];
    const void*  tgt = d_in[1];
    float*       out = (float*)d_out;

    int n = in_sizes[1];            // 8192
    int nt = n / BM;                // 64
    int ntri = nt * (nt + 1) / 2;   // 2080

    static int smem_set = 0;
    if (!smem_set) {
        cudaFuncSetAttribute(loss_kernel, cudaFuncAttributeMaxDynamicSharedMemorySize, SM_TOTAL);
        smem_set = 1;
    }

    cvtsq_kernel<<<(n + 7) / 8, 256>>>(x, (const unsigned int*)tgt, n, out);

    float scale = (float)(1.0 / ((double)n * ((double)n - 1.0)));
    loss_kernel<<<NCTA, NTHREADS, SM_TOTAL>>>(tgt, out, nt, ntri, scale);
}